// round 3
// baseline (speedup 1.0000x reference)
#include <cuda_runtime.h>

// Problem constants
#define NB   4
#define SEQ  2048
#define VD   1024
#define H    16
#define HD   64
#define QT   128      // query rows per attention CTA
#define KT   64       // key rows per inner block

// Scratch: per-head-projected Q,K,V in [n,h,s,d] layout, and pre-Wo attention
// output in [n,s,voxel] layout. __device__ globals (no runtime allocation),
// referenced directly from device code — no cudaGetSymbolAddress needed.
__device__ float g_Qp[(size_t)NB * H * SEQ * HD];
__device__ float g_Kp[(size_t)NB * H * SEQ * HD];
__device__ float g_Vp[(size_t)NB * H * SEQ * HD];
__device__ float g_att[(size_t)NB * SEQ * VD];

// ---------------------------------------------------------------------------
// Kernel 1: per-head projection  Y[n,h,s,e] = scale*(sum_d X[n,s,h*64+d]*W[h,d,e] + b[h,e])
// dst: 0 -> g_Qp, 1 -> g_Kp, 2 -> g_Vp
// grid: (SEQ/64, H, NB), block: 256
// ---------------------------------------------------------------------------
__global__ __launch_bounds__(256) void proj_kernel(
    const float* __restrict__ X, const float* __restrict__ W,
    const float* __restrict__ b, int dst, float scale)
{
    __shared__ float Ws[HD * HD];   // [d][e]
    __shared__ float bs[HD];
    __shared__ float Xs[64 * HD];   // [r][d]

    float* __restrict__ Y = (dst == 0) ? g_Qp : (dst == 1) ? g_Kp : g_Vp;

    const int h = blockIdx.y, n = blockIdx.z;
    const int s0 = blockIdx.x * 64;
    const int tid = threadIdx.x;

    // load W[h] (4096 floats) and bias
    {
        const float4* Wg = (const float4*)(W + (size_t)h * HD * HD);
        float4* Ws4 = (float4*)Ws;
        #pragma unroll
        for (int i = tid; i < HD * HD / 4; i += 256) Ws4[i] = Wg[i];
        if (tid < HD) bs[tid] = b[h * HD + tid] * scale;
    }
    // load X tile: 64 rows x 64 cols (head slice)
    for (int i = tid; i < 64 * HD / 4; i += 256) {
        int r  = i / (HD / 4);
        int c4 = (i % (HD / 4)) * 4;
        *(float4*)(Xs + r * HD + c4) =
            *(const float4*)(X + ((size_t)(n * SEQ + s0 + r)) * VD + h * HD + c4);
    }
    __syncthreads();

    const int ty = tid / 16;   // row group: rows ty*4 .. ty*4+3
    const int tx = tid % 16;   // col group: cols tx*4 .. tx*4+3

    float acc[4][4];
    #pragma unroll
    for (int i = 0; i < 4; i++)
        #pragma unroll
        for (int j = 0; j < 4; j++) acc[i][j] = 0.f;

    #pragma unroll 8
    for (int k = 0; k < HD; k++) {
        const float4 bv = *(const float4*)(Ws + k * HD + tx * 4);
        #pragma unroll
        for (int i = 0; i < 4; i++) {
            const float a = Xs[(ty * 4 + i) * HD + k];
            acc[i][0] += a * bv.x; acc[i][1] += a * bv.y;
            acc[i][2] += a * bv.z; acc[i][3] += a * bv.w;
        }
    }

    #pragma unroll
    for (int i = 0; i < 4; i++) {
        const int s = s0 + ty * 4 + i;
        float4 o;
        o.x = acc[i][0] * scale + bs[tx * 4 + 0];
        o.y = acc[i][1] * scale + bs[tx * 4 + 1];
        o.z = acc[i][2] * scale + bs[tx * 4 + 2];
        o.w = acc[i][3] * scale + bs[tx * 4 + 3];
        *(float4*)(Y + ((size_t)((n * H + h) * SEQ + s)) * HD + tx * 4) = o;
    }
}

// ---------------------------------------------------------------------------
// Kernel 2: flash attention per (n,h): O = softmax(Q Kᵀ) V  (Q pre-scaled by 1/32)
// grid: (SEQ/QT, H, NB), block 256, dynamic smem.
// SMEM: Qs[128*64] | Ks[64(d)*64(kv)] (transposed) | Vs[64(kv)*64(d)] |
//       Ss[128*64] | alphaS[128] | lS[128] | msk[64]
// ---------------------------------------------------------------------------
#define ATTN_SMEM_FLOATS (QT*HD + HD*KT + KT*HD + QT*KT + QT + QT + KT)
#define ATTN_SMEM_BYTES  (ATTN_SMEM_FLOATS * 4)

__global__ __launch_bounds__(256, 2) void attn_kernel(const int* __restrict__ mask)
{
    extern __shared__ float sm[];
    float* Qs     = sm;                    // [r][d]
    float* Ks     = Qs + QT * HD;          // [d][kv]
    float* Vs     = Ks + HD * KT;          // [kv][d]
    float* Ss     = Vs + KT * HD;          // [r][kv]
    float* alphaS = Ss + QT * KT;          // [r]
    float* lS     = alphaS + QT;           // [r]
    int*   msk    = (int*)(lS + QT);       // [kv]

    const int h = blockIdx.y, n = blockIdx.z;
    const int q0 = blockIdx.x * QT;
    const int tid = threadIdx.x;
    const int ty = tid / 16;               // rows ty*8 .. +7
    const int tx = tid % 16;               // cols tx*4 .. +3

    const size_t head_off = (size_t)(n * H + h) * SEQ * HD;
    const float* Qg = g_Qp + head_off;
    const float* Kg = g_Kp + head_off;
    const float* Vg = g_Vp + head_off;

    // load Q tile (stays resident)
    for (int i = tid; i < QT * HD / 4; i += 256)
        ((float4*)Qs)[i] = ((const float4*)(Qg + (size_t)q0 * HD))[i];

    float m_r = -1e30f, l_r = 0.f;   // valid for tid < QT (row = tid)
    float O[8][4];
    #pragma unroll
    for (int i = 0; i < 8; i++)
        #pragma unroll
        for (int j = 0; j < 4; j++) O[i][j] = 0.f;

    for (int kb = 0; kb < SEQ / KT; kb++) {
        __syncthreads();   // prior-iteration consumers done; also covers Q load at kb=0

        // load K (transposed -> Ks[d][kv]) and V (natural -> Vs[kv][d])
        const int kv0 = kb * KT;
        for (int i = tid; i < KT * HD / 4; i += 256) {
            const int r  = i / (HD / 4);
            const int c4 = (i % (HD / 4)) * 4;
            const float4 kk = *(const float4*)(Kg + (size_t)(kv0 + r) * HD + c4);
            Ks[(c4 + 0) * KT + r] = kk.x;
            Ks[(c4 + 1) * KT + r] = kk.y;
            Ks[(c4 + 2) * KT + r] = kk.z;
            Ks[(c4 + 3) * KT + r] = kk.w;
            *(float4*)(Vs + r * HD + c4) =
                *(const float4*)(Vg + (size_t)(kv0 + r) * HD + c4);
        }
        if (tid < KT) msk[tid] = mask[n * SEQ + kv0 + tid];
        __syncthreads();

        // GEMM1: S = Q @ Kᵀ  (Q pre-scaled)
        float acc[8][4];
        #pragma unroll
        for (int i = 0; i < 8; i++)
            #pragma unroll
            for (int j = 0; j < 4; j++) acc[i][j] = 0.f;

        const float* Qrow = Qs + ty * 8 * HD;
        #pragma unroll 8
        for (int d = 0; d < HD; d++) {
            const float4 kv = *(const float4*)(Ks + d * KT + tx * 4);
            #pragma unroll
            for (int i = 0; i < 8; i++) {
                const float a = Qrow[i * HD + d];
                acc[i][0] += a * kv.x; acc[i][1] += a * kv.y;
                acc[i][2] += a * kv.z; acc[i][3] += a * kv.w;
            }
        }
        // apply mask, store S to smem
        const bool z0 = (msk[tx * 4 + 0] == 0);
        const bool z1 = (msk[tx * 4 + 1] == 0);
        const bool z2 = (msk[tx * 4 + 2] == 0);
        const bool z3 = (msk[tx * 4 + 3] == 0);
        #pragma unroll
        for (int i = 0; i < 8; i++) {
            float4 o;
            o.x = z0 ? -1e30f : acc[i][0];
            o.y = z1 ? -1e30f : acc[i][1];
            o.z = z2 ? -1e30f : acc[i][2];
            o.w = z3 ? -1e30f : acc[i][3];
            *(float4*)(Ss + (ty * 8 + i) * KT + tx * 4) = o;
        }
        __syncthreads();

        // online softmax: one thread per row; lane-rotated access avoids bank conflicts
        if (tid < QT) {
            float* Sr = Ss + tid * KT;
            float mnew = m_r;
            #pragma unroll 8
            for (int j = 0; j < KT; j++) {
                const int jj = (j + tid) & (KT - 1);
                mnew = fmaxf(mnew, Sr[jj]);
            }
            const float al = __expf(m_r - mnew);
            float ssum = 0.f;
            #pragma unroll 8
            for (int j = 0; j < KT; j++) {
                const int jj = (j + tid) & (KT - 1);
                const float p = __expf(Sr[jj] - mnew);
                Sr[jj] = p;
                ssum += p;
            }
            l_r = l_r * al + ssum;
            m_r = mnew;
            alphaS[tid] = al;
        }
        __syncthreads();

        // GEMM2: O = O*alpha + P @ V
        #pragma unroll
        for (int i = 0; i < 8; i++) {
            const float al = alphaS[ty * 8 + i];
            O[i][0] *= al; O[i][1] *= al; O[i][2] *= al; O[i][3] *= al;
        }
        const float* Srow = Ss + ty * 8 * KT;
        #pragma unroll 8
        for (int kk = 0; kk < KT; kk++) {
            const float4 vv = *(const float4*)(Vs + kk * HD + tx * 4);
            #pragma unroll
            for (int i = 0; i < 8; i++) {
                const float p = Srow[i * KT + kk];
                O[i][0] += p * vv.x; O[i][1] += p * vv.y;
                O[i][2] += p * vv.z; O[i][3] += p * vv.w;
            }
        }
    }

    // normalize and write to g_att[n, q, h*64 + d]
    if (tid < QT) lS[tid] = 1.f / l_r;
    __syncthreads();
    #pragma unroll
    for (int i = 0; i < 8; i++) {
        const float inv = lS[ty * 8 + i];
        float4 o;
        o.x = O[i][0] * inv; o.y = O[i][1] * inv;
        o.z = O[i][2] * inv; o.w = O[i][3] * inv;
        const int q = q0 + ty * 8 + i;
        *(float4*)(g_att + ((size_t)n * SEQ + q) * VD + h * HD + tx * 4) = o;
    }
}

// ---------------------------------------------------------------------------
// Kernel 3: output projection  out[s,j] = sum_d g_att[s,d] * Wo[j,d] + bo[j]
// grid: (VD/128, NB*SEQ/128), block 256, 128x128x16 tiles, 8x8 per thread.
// ---------------------------------------------------------------------------
#define WTM 128
#define WTN 128
#define WTK 16

__global__ __launch_bounds__(256, 2) void wo_kernel(
    const float* __restrict__ Wo, const float* __restrict__ bo,
    float* __restrict__ out)
{
    __shared__ float As[WTM * WTK];   // [r][k]
    __shared__ float Bs[WTK * WTN];   // [k][j]

    const int j0 = blockIdx.x * WTN;
    const int r0 = blockIdx.y * WTM;
    const int tid = threadIdx.x;
    const int ty = tid / 16;          // rows ty*8 .. +7
    const int tx = tid % 16;          // cols tx*8 .. +7

    float acc[8][8];
    #pragma unroll
    for (int i = 0; i < 8; i++)
        #pragma unroll
        for (int j = 0; j < 8; j++) acc[i][j] = 0.f;

    for (int k0 = 0; k0 < VD; k0 += WTK) {
        __syncthreads();
        // A tile: 128 rows x 16 k
        for (int i = tid; i < WTM * WTK / 4; i += 256) {
            const int r  = i >> 2;
            const int k4 = (i & 3) * 4;
            *(float4*)(As + r * WTK + k4) =
                *(const float4*)(g_att + (size_t)(r0 + r) * VD + k0 + k4);
        }
        // B tile: Wo[j][k] transposed -> Bs[k][j]
        for (int i = tid; i < WTN * WTK / 4; i += 256) {
            const int j  = i >> 2;
            const int k4 = (i & 3) * 4;
            const float4 w = *(const float4*)(Wo + (size_t)(j0 + j) * VD + k0 + k4);
            Bs[(k4 + 0) * WTN + j] = w.x;
            Bs[(k4 + 1) * WTN + j] = w.y;
            Bs[(k4 + 2) * WTN + j] = w.z;
            Bs[(k4 + 3) * WTN + j] = w.w;
        }
        __syncthreads();

        #pragma unroll
        for (int k = 0; k < WTK; k++) {
            const float4 b0 = *(const float4*)(Bs + k * WTN + tx * 8);
            const float4 b1 = *(const float4*)(Bs + k * WTN + tx * 8 + 4);
            float a[8];
            #pragma unroll
            for (int i = 0; i < 8; i++) a[i] = As[(ty * 8 + i) * WTK + k];
            #pragma unroll
            for (int i = 0; i < 8; i++) {
                acc[i][0] += a[i] * b0.x; acc[i][1] += a[i] * b0.y;
                acc[i][2] += a[i] * b0.z; acc[i][3] += a[i] * b0.w;
                acc[i][4] += a[i] * b1.x; acc[i][5] += a[i] * b1.y;
                acc[i][6] += a[i] * b1.z; acc[i][7] += a[i] * b1.w;
            }
        }
    }

    const float4 bb0 = *(const float4*)(bo + j0 + tx * 8);
    const float4 bb1 = *(const float4*)(bo + j0 + tx * 8 + 4);
    #pragma unroll
    for (int i = 0; i < 8; i++) {
        const int r = r0 + ty * 8 + i;
        float4 o0, o1;
        o0.x = acc[i][0] + bb0.x; o0.y = acc[i][1] + bb0.y;
        o0.z = acc[i][2] + bb0.z; o0.w = acc[i][3] + bb0.w;
        o1.x = acc[i][4] + bb1.x; o1.y = acc[i][5] + bb1.y;
        o1.z = acc[i][6] + bb1.z; o1.w = acc[i][7] + bb1.w;
        *(float4*)(out + (size_t)r * VD + j0 + tx * 8)     = o0;
        *(float4*)(out + (size_t)r * VD + j0 + tx * 8 + 4) = o1;
    }
}

// ---------------------------------------------------------------------------
// Host launcher (graph-capturable: kernel launches only; the attribute set
// executes host-side at capture time and is required for >48KB dynamic smem)
// ---------------------------------------------------------------------------
extern "C" void kernel_launch(void* const* d_in, const int* in_sizes, int n_in,
                              void* d_out, int out_size)
{
    const float* values = (const float*)d_in[0];
    const float* keys   = (const float*)d_in[1];
    const float* query  = (const float*)d_in[2];
    const int*   mask   = (const int*)  d_in[3];
    const float* Wv     = (const float*)d_in[4];
    const float* bv     = (const float*)d_in[5];
    const float* Wk     = (const float*)d_in[6];
    const float* bk     = (const float*)d_in[7];
    const float* Wq     = (const float*)d_in[8];
    const float* bq     = (const float*)d_in[9];
    const float* Wo     = (const float*)d_in[10];
    const float* bo     = (const float*)d_in[11];
    float* out = (float*)d_out;

    cudaFuncSetAttribute(attn_kernel, cudaFuncAttributeMaxDynamicSharedMemorySize,
                         ATTN_SMEM_BYTES);

    const dim3 pgrid(SEQ / 64, H, NB);
    // Q projection pre-scaled by 1/sqrt(VOXEL_DIM) = 1/32
    proj_kernel<<<pgrid, 256>>>(query,  Wq, bq, /*dst=*/0, 1.0f / 32.0f);
    proj_kernel<<<pgrid, 256>>>(keys,   Wk, bk, /*dst=*/1, 1.0f);
    proj_kernel<<<pgrid, 256>>>(values, Wv, bv, /*dst=*/2, 1.0f);

    attn_kernel<<<dim3(SEQ / QT, H, NB), 256, ATTN_SMEM_BYTES>>>(mask);

    wo_kernel<<<dim3(VD / WTN, (NB * SEQ) / WTM), 256>>>(Wo, bo, out);
}

// round 4
// speedup vs baseline: 1.9429x; 1.9429x over previous
#include <cuda_runtime.h>
#include <cstdint>

// Problem constants
#define NB   4
#define SEQ  2048
#define VD   1024
#define H    16
#define HD   64
#define QT   128      // query rows per attention CTA
#define KT   64       // key rows per inner block
#define PAD  68       // smem row stride (floats) — 68 mod 32 = 4 → conflict-free frag access

// Scratch (__device__ globals, no runtime allocation)
__device__ float g_Qp[(size_t)NB * H * SEQ * HD];
__device__ float g_Kp[(size_t)NB * H * SEQ * HD];
__device__ float g_Vp[(size_t)NB * H * SEQ * HD];
__device__ float g_att[(size_t)NB * SEQ * VD];

// ---------------------------------------------------------------------------
// tf32 helpers
// ---------------------------------------------------------------------------
__device__ __forceinline__ unsigned f2tf(float f) {
    unsigned u;
    asm("cvt.rna.tf32.f32 %0, %1;" : "=r"(u) : "f"(f));
    return u;
}

// D = A*B + C  (m16n8k8, tf32 in, f32 acc), C==D in-place
__device__ __forceinline__ void mma_tf32(float c[4],
    unsigned a0, unsigned a1, unsigned a2, unsigned a3,
    unsigned b0, unsigned b1)
{
    asm volatile(
        "mma.sync.aligned.m16n8k8.row.col.f32.tf32.tf32.f32 "
        "{%0,%1,%2,%3}, {%4,%5,%6,%7}, {%8,%9}, {%0,%1,%2,%3};\n"
        : "+f"(c[0]), "+f"(c[1]), "+f"(c[2]), "+f"(c[3])
        : "r"(a0), "r"(a1), "r"(a2), "r"(a3), "r"(b0), "r"(b1));
}

// ---------------------------------------------------------------------------
// Kernel 1: per-head projection  Y[n,h,s,e] = scale*(sum_d X[n,s,h*64+d]*W[h,d,e]) + scale*b
// dst: 0 -> g_Qp, 1 -> g_Kp, 2 -> g_Vp.  grid (SEQ/64, H, NB), block 256.
// ---------------------------------------------------------------------------
__global__ __launch_bounds__(256) void proj_kernel(
    const float* __restrict__ X, const float* __restrict__ W,
    const float* __restrict__ b, int dst, float scale)
{
    __shared__ float Ws[HD * HD];   // [d][e]
    __shared__ float bs[HD];
    __shared__ float Xs[64 * HD];   // [r][d]

    float* __restrict__ Y = (dst == 0) ? g_Qp : (dst == 1) ? g_Kp : g_Vp;

    const int h = blockIdx.y, n = blockIdx.z;
    const int s0 = blockIdx.x * 64;
    const int tid = threadIdx.x;

    {
        const float4* Wg = (const float4*)(W + (size_t)h * HD * HD);
        float4* Ws4 = (float4*)Ws;
        #pragma unroll
        for (int i = tid; i < HD * HD / 4; i += 256) Ws4[i] = Wg[i];
        if (tid < HD) bs[tid] = b[h * HD + tid] * scale;
    }
    for (int i = tid; i < 64 * HD / 4; i += 256) {
        int r  = i / (HD / 4);
        int c4 = (i % (HD / 4)) * 4;
        *(float4*)(Xs + r * HD + c4) =
            *(const float4*)(X + ((size_t)(n * SEQ + s0 + r)) * VD + h * HD + c4);
    }
    __syncthreads();

    const int ty = tid / 16;
    const int tx = tid % 16;

    float acc[4][4];
    #pragma unroll
    for (int i = 0; i < 4; i++)
        #pragma unroll
        for (int j = 0; j < 4; j++) acc[i][j] = 0.f;

    #pragma unroll 8
    for (int k = 0; k < HD; k++) {
        const float4 bv = *(const float4*)(Ws + k * HD + tx * 4);
        #pragma unroll
        for (int i = 0; i < 4; i++) {
            const float a = Xs[(ty * 4 + i) * HD + k];
            acc[i][0] += a * bv.x; acc[i][1] += a * bv.y;
            acc[i][2] += a * bv.z; acc[i][3] += a * bv.w;
        }
    }

    #pragma unroll
    for (int i = 0; i < 4; i++) {
        const int s = s0 + ty * 4 + i;
        float4 o;
        o.x = acc[i][0] * scale + bs[tx * 4 + 0];
        o.y = acc[i][1] * scale + bs[tx * 4 + 1];
        o.z = acc[i][2] * scale + bs[tx * 4 + 2];
        o.w = acc[i][3] * scale + bs[tx * 4 + 3];
        *(float4*)(Y + ((size_t)((n * H + h) * SEQ + s)) * HD + tx * 4) = o;
    }
}

// ---------------------------------------------------------------------------
// Kernel 2: flash attention per (n,h), tf32 tensor-core MMAs, register softmax.
// Block 256 = 8 warps; warp w owns q-rows [16w,16w+16). grid (SEQ/QT, H, NB).
// SMEM (all tf32 uints, row stride PAD=68):
//   QsU[128][68] | SsU[128][68] (P) | KsU[64][68] | VsU[64][68] | msk[64]
// Fragment maps (m16n8k8, lane = 4g+t):
//   A: a0(g,t) a1(g+8,t) a2(g,t+4) a3(g+8,t+4)   [row-major m x k]
//   B: b0(t,g) b1(t+4,g)                          [col-major k x n]
//   C: c0(g,2t) c1(g,2t+1) c2(g+8,2t) c3(g+8,2t+1)
// ---------------------------------------------------------------------------
#define ATTN_SMEM_BYTES (((QT + QT + KT + KT) * PAD) * 4 + KT * 4)

__global__ __launch_bounds__(256, 2) void attn_kernel(const int* __restrict__ mask)
{
    extern __shared__ unsigned smu[];
    unsigned* QsU = smu;                   // [QT][PAD]
    unsigned* SsU = QsU + QT * PAD;        // [QT][PAD]  (P tile)
    unsigned* KsU = SsU + QT * PAD;        // [KT][PAD]  natural [kv][d]
    unsigned* VsU = KsU + KT * PAD;        // [KT][PAD]  natural [kv][d]
    int*      msk = (int*)(VsU + KT * PAD);

    const int h = blockIdx.y, n = blockIdx.z;
    const int q0 = blockIdx.x * QT;
    const int tid  = threadIdx.x;
    const int wid  = tid >> 5;
    const int lane = tid & 31;
    const int g = lane >> 2;
    const int t = lane & 3;
    const int qrow = wid * 16;

    const size_t head_off = (size_t)(n * H + h) * SEQ * HD;
    const float* Qg = g_Qp + head_off + (size_t)q0 * HD;
    const float* Kg = g_Kp + head_off;
    const float* Vg = g_Vp + head_off;

    // stage Q as tf32 (natural layout [q][d])
    for (int i = tid; i < QT * HD / 4; i += 256) {
        const int r  = i >> 4;
        const int c4 = (i & 15) * 4;
        const float4 q = *(const float4*)(Qg + (size_t)r * HD + c4);
        unsigned* dst = QsU + r * PAD + c4;
        dst[0] = f2tf(q.x); dst[1] = f2tf(q.y); dst[2] = f2tf(q.z); dst[3] = f2tf(q.w);
    }

    float O[8][4];
    #pragma unroll
    for (int j = 0; j < 8; j++)
        #pragma unroll
        for (int i = 0; i < 4; i++) O[j][i] = 0.f;
    float m0 = -1e30f, m1 = -1e30f, l0 = 0.f, l1 = 0.f;

    for (int kb = 0; kb < SEQ / KT; kb++) {
        __syncthreads();   // previous iteration consumers done (also covers Q stage at kb=0)
        const int kv0 = kb * KT;

        // load K and V tiles (natural [kv][d], tf32)
        for (int i = tid; i < KT * HD / 4; i += 256) {
            const int r  = i >> 4;
            const int c4 = (i & 15) * 4;
            const float4 kk = *(const float4*)(Kg + (size_t)(kv0 + r) * HD + c4);
            unsigned* kd = KsU + r * PAD + c4;
            kd[0] = f2tf(kk.x); kd[1] = f2tf(kk.y); kd[2] = f2tf(kk.z); kd[3] = f2tf(kk.w);
            const float4 vv = *(const float4*)(Vg + (size_t)(kv0 + r) * HD + c4);
            unsigned* vd = VsU + r * PAD + c4;
            vd[0] = f2tf(vv.x); vd[1] = f2tf(vv.y); vd[2] = f2tf(vv.z); vd[3] = f2tf(vv.w);
        }
        if (tid < KT) msk[tid] = mask[n * SEQ + kv0 + tid];
        __syncthreads();

        // ---- GEMM1: S[16 x 64] = Q · Kᵀ  (B(k=d, n=kv) col-major = K[kv][d]) ----
        float S[8][4];
        #pragma unroll
        for (int j = 0; j < 8; j++)
            #pragma unroll
            for (int i = 0; i < 4; i++) S[j][i] = 0.f;

        #pragma unroll
        for (int kk = 0; kk < 8; kk++) {
            const unsigned a0 = QsU[(qrow + g)     * PAD + kk * 8 + t];
            const unsigned a1 = QsU[(qrow + g + 8) * PAD + kk * 8 + t];
            const unsigned a2 = QsU[(qrow + g)     * PAD + kk * 8 + t + 4];
            const unsigned a3 = QsU[(qrow + g + 8) * PAD + kk * 8 + t + 4];
            #pragma unroll
            for (int j = 0; j < 8; j++) {
                const unsigned b0 = KsU[(j * 8 + g) * PAD + kk * 8 + t];
                const unsigned b1 = KsU[(j * 8 + g) * PAD + kk * 8 + t + 4];
                mma_tf32(S[j], a0, a1, a2, a3, b0, b1);
            }
        }

        // ---- mask + online softmax (register-resident, C-frag layout) ----
        #pragma unroll
        for (int j = 0; j < 8; j++) {
            if (msk[j * 8 + 2 * t]     == 0) { S[j][0] = -1e30f; S[j][2] = -1e30f; }
            if (msk[j * 8 + 2 * t + 1] == 0) { S[j][1] = -1e30f; S[j][3] = -1e30f; }
        }
        float mn0 = m0, mn1 = m1;
        #pragma unroll
        for (int j = 0; j < 8; j++) {
            mn0 = fmaxf(mn0, fmaxf(S[j][0], S[j][1]));
            mn1 = fmaxf(mn1, fmaxf(S[j][2], S[j][3]));
        }
        mn0 = fmaxf(mn0, __shfl_xor_sync(0xffffffffu, mn0, 1));
        mn0 = fmaxf(mn0, __shfl_xor_sync(0xffffffffu, mn0, 2));
        mn1 = fmaxf(mn1, __shfl_xor_sync(0xffffffffu, mn1, 1));
        mn1 = fmaxf(mn1, __shfl_xor_sync(0xffffffffu, mn1, 2));

        const float al0 = __expf(m0 - mn0);
        const float al1 = __expf(m1 - mn1);
        m0 = mn0; m1 = mn1;

        float s0 = 0.f, s1 = 0.f;
        unsigned* Prow0 = SsU + (qrow + g)     * PAD + 2 * t;
        unsigned* Prow1 = SsU + (qrow + g + 8) * PAD + 2 * t;
        #pragma unroll
        for (int j = 0; j < 8; j++) {
            const float p00 = __expf(S[j][0] - mn0);
            const float p01 = __expf(S[j][1] - mn0);
            const float p10 = __expf(S[j][2] - mn1);
            const float p11 = __expf(S[j][3] - mn1);
            s0 += p00 + p01;
            s1 += p10 + p11;
            *(uint2*)(Prow0 + j * 8) = make_uint2(f2tf(p00), f2tf(p01));
            *(uint2*)(Prow1 + j * 8) = make_uint2(f2tf(p10), f2tf(p11));
        }
        s0 += __shfl_xor_sync(0xffffffffu, s0, 1);
        s0 += __shfl_xor_sync(0xffffffffu, s0, 2);
        s1 += __shfl_xor_sync(0xffffffffu, s1, 1);
        s1 += __shfl_xor_sync(0xffffffffu, s1, 2);
        l0 = l0 * al0 + s0;
        l1 = l1 * al1 + s1;

        #pragma unroll
        for (int j = 0; j < 8; j++) {
            O[j][0] *= al0; O[j][1] *= al0;
            O[j][2] *= al1; O[j][3] *= al1;
        }
        __syncwarp();   // P stores visible to sibling lanes (Ss is per-warp private)

        // ---- GEMM2: O[16 x 64] += P · V  (B(k=kv, n=d) col-major = V[kv][d]) ----
        #pragma unroll
        for (int kk = 0; kk < 8; kk++) {
            const unsigned a0 = SsU[(qrow + g)     * PAD + kk * 8 + t];
            const unsigned a1 = SsU[(qrow + g + 8) * PAD + kk * 8 + t];
            const unsigned a2 = SsU[(qrow + g)     * PAD + kk * 8 + t + 4];
            const unsigned a3 = SsU[(qrow + g + 8) * PAD + kk * 8 + t + 4];
            #pragma unroll
            for (int j = 0; j < 8; j++) {
                const unsigned b0 = VsU[(kk * 8 + t)     * PAD + j * 8 + g];
                const unsigned b1 = VsU[(kk * 8 + t + 4) * PAD + j * 8 + g];
                mma_tf32(O[j], a0, a1, a2, a3, b0, b1);
            }
        }
    }

    // epilogue: normalize, write g_att[n, q, h*64+d]
    const float inv0 = 1.f / l0, inv1 = 1.f / l1;
    float* Og = g_att + ((size_t)n * SEQ + q0 + qrow) * VD + h * HD;
    #pragma unroll
    for (int j = 0; j < 8; j++) {
        float2 o0 = make_float2(O[j][0] * inv0, O[j][1] * inv0);
        float2 o1 = make_float2(O[j][2] * inv1, O[j][3] * inv1);
        *(float2*)(Og + (size_t)g       * VD + j * 8 + 2 * t) = o0;
        *(float2*)(Og + (size_t)(g + 8) * VD + j * 8 + 2 * t) = o1;
    }
}

// ---------------------------------------------------------------------------
// Kernel 3: output projection  out[s,j] = sum_d g_att[s,d] * Wo[j,d] + bo[j]
// (kept fp32 FFMA this round for precision headroom)
// ---------------------------------------------------------------------------
#define WTM 128
#define WTN 128
#define WTK 16

__global__ __launch_bounds__(256, 2) void wo_kernel(
    const float* __restrict__ Wo, const float* __restrict__ bo,
    float* __restrict__ out)
{
    __shared__ float As[WTM * WTK];   // [r][k]
    __shared__ float Bs[WTK * WTN];   // [k][j]

    const int j0 = blockIdx.x * WTN;
    const int r0 = blockIdx.y * WTM;
    const int tid = threadIdx.x;
    const int ty = tid / 16;
    const int tx = tid % 16;

    float acc[8][8];
    #pragma unroll
    for (int i = 0; i < 8; i++)
        #pragma unroll
        for (int j = 0; j < 8; j++) acc[i][j] = 0.f;

    for (int k0 = 0; k0 < VD; k0 += WTK) {
        __syncthreads();
        for (int i = tid; i < WTM * WTK / 4; i += 256) {
            const int r  = i >> 2;
            const int k4 = (i & 3) * 4;
            *(float4*)(As + r * WTK + k4) =
                *(const float4*)(g_att + (size_t)(r0 + r) * VD + k0 + k4);
        }
        for (int i = tid; i < WTN * WTK / 4; i += 256) {
            const int j  = i >> 2;
            const int k4 = (i & 3) * 4;
            const float4 w = *(const float4*)(Wo + (size_t)(j0 + j) * VD + k0 + k4);
            Bs[(k4 + 0) * WTN + j] = w.x;
            Bs[(k4 + 1) * WTN + j] = w.y;
            Bs[(k4 + 2) * WTN + j] = w.z;
            Bs[(k4 + 3) * WTN + j] = w.w;
        }
        __syncthreads();

        #pragma unroll
        for (int k = 0; k < WTK; k++) {
            const float4 b0 = *(const float4*)(Bs + k * WTN + tx * 8);
            const float4 b1 = *(const float4*)(Bs + k * WTN + tx * 8 + 4);
            float a[8];
            #pragma unroll
            for (int i = 0; i < 8; i++) a[i] = As[(ty * 8 + i) * WTK + k];
            #pragma unroll
            for (int i = 0; i < 8; i++) {
                acc[i][0] += a[i] * b0.x; acc[i][1] += a[i] * b0.y;
                acc[i][2] += a[i] * b0.z; acc[i][3] += a[i] * b0.w;
                acc[i][4] += a[i] * b1.x; acc[i][5] += a[i] * b1.y;
                acc[i][6] += a[i] * b1.z; acc[i][7] += a[i] * b1.w;
            }
        }
    }

    const float4 bb0 = *(const float4*)(bo + j0 + tx * 8);
    const float4 bb1 = *(const float4*)(bo + j0 + tx * 8 + 4);
    #pragma unroll
    for (int i = 0; i < 8; i++) {
        const int r = r0 + ty * 8 + i;
        float4 o0, o1;
        o0.x = acc[i][0] + bb0.x; o0.y = acc[i][1] + bb0.y;
        o0.z = acc[i][2] + bb0.z; o0.w = acc[i][3] + bb0.w;
        o1.x = acc[i][4] + bb1.x; o1.y = acc[i][5] + bb1.y;
        o1.z = acc[i][6] + bb1.z; o1.w = acc[i][7] + bb1.w;
        *(float4*)(out + (size_t)r * VD + j0 + tx * 8)     = o0;
        *(float4*)(out + (size_t)r * VD + j0 + tx * 8 + 4) = o1;
    }
}

// ---------------------------------------------------------------------------
// Host launcher (graph-capturable: kernel launches only)
// ---------------------------------------------------------------------------
extern "C" void kernel_launch(void* const* d_in, const int* in_sizes, int n_in,
                              void* d_out, int out_size)
{
    const float* values = (const float*)d_in[0];
    const float* keys   = (const float*)d_in[1];
    const float* query  = (const float*)d_in[2];
    const int*   mask   = (const int*)  d_in[3];
    const float* Wv     = (const float*)d_in[4];
    const float* bv     = (const float*)d_in[5];
    const float* Wk     = (const float*)d_in[6];
    const float* bk     = (const float*)d_in[7];
    const float* Wq     = (const float*)d_in[8];
    const float* bq     = (const float*)d_in[9];
    const float* Wo     = (const float*)d_in[10];
    const float* bo     = (const float*)d_in[11];
    float* out = (float*)d_out;

    cudaFuncSetAttribute(attn_kernel, cudaFuncAttributeMaxDynamicSharedMemorySize,
                         ATTN_SMEM_BYTES);

    const dim3 pgrid(SEQ / 64, H, NB);
    // Q projection pre-scaled by 1/sqrt(VOXEL_DIM) = 1/32
    proj_kernel<<<pgrid, 256>>>(query,  Wq, bq, /*dst=*/0, 1.0f / 32.0f);
    proj_kernel<<<pgrid, 256>>>(keys,   Wk, bk, /*dst=*/1, 1.0f);
    proj_kernel<<<pgrid, 256>>>(values, Wv, bv, /*dst=*/2, 1.0f);

    attn_kernel<<<dim3(SEQ / QT, H, NB), 256, ATTN_SMEM_BYTES>>>(mask);

    wo_kernel<<<dim3(VD / WTN, (NB * SEQ) / WTM), 256>>>(Wo, bo, out);
}

// round 5
// speedup vs baseline: 1.9469x; 1.0020x over previous
#include <cuda_runtime.h>
#include <cstdint>

// Problem constants
#define NB   4
#define SEQ  2048
#define VD   1024
#define H    16
#define HD   64
#define QT   128      // query rows per attention CTA
#define KT   64       // key rows per inner block
#define PAD  68       // smem row stride (floats) — 68 mod 32 = 4 → conflict-free frag access

// Scratch (__device__ globals, no runtime allocation)
__device__ float g_Qp[(size_t)NB * H * SEQ * HD];
__device__ float g_Kp[(size_t)NB * H * SEQ * HD];
__device__ float g_Vp[(size_t)NB * H * SEQ * HD];
__device__ float g_att[(size_t)NB * SEQ * VD];

// ---------------------------------------------------------------------------
// tf32 helpers
// ---------------------------------------------------------------------------
__device__ __forceinline__ unsigned f2tf(float f) {
    unsigned u;
    asm("cvt.rna.tf32.f32 %0, %1;" : "=r"(u) : "f"(f));
    return u;
}

// D = A*B + C  (m16n8k8, tf32 in, f32 acc), C==D in-place
__device__ __forceinline__ void mma_tf32(float c[4],
    unsigned a0, unsigned a1, unsigned a2, unsigned a3,
    unsigned b0, unsigned b1)
{
    asm volatile(
        "mma.sync.aligned.m16n8k8.row.col.f32.tf32.tf32.f32 "
        "{%0,%1,%2,%3}, {%4,%5,%6,%7}, {%8,%9}, {%0,%1,%2,%3};\n"
        : "+f"(c[0]), "+f"(c[1]), "+f"(c[2]), "+f"(c[3])
        : "r"(a0), "r"(a1), "r"(a2), "r"(a3), "r"(b0), "r"(b1));
}

// ---------------------------------------------------------------------------
// Kernel 1: per-head projection  Y[n,h,s,e] = scale*(sum_d X[n,s,h*64+d]*W[h,d,e]) + scale*b
// dst: 0 -> g_Qp, 1 -> g_Kp, 2 -> g_Vp.  grid (SEQ/64, H, NB), block 256.
// ---------------------------------------------------------------------------
__global__ __launch_bounds__(256) void proj_kernel(
    const float* __restrict__ X, const float* __restrict__ W,
    const float* __restrict__ b, int dst, float scale)
{
    __shared__ float Ws[HD * HD];   // [d][e]
    __shared__ float bs[HD];
    __shared__ float Xs[64 * HD];   // [r][d]

    float* __restrict__ Y = (dst == 0) ? g_Qp : (dst == 1) ? g_Kp : g_Vp;

    const int h = blockIdx.y, n = blockIdx.z;
    const int s0 = blockIdx.x * 64;
    const int tid = threadIdx.x;

    {
        const float4* Wg = (const float4*)(W + (size_t)h * HD * HD);
        float4* Ws4 = (float4*)Ws;
        #pragma unroll
        for (int i = tid; i < HD * HD / 4; i += 256) Ws4[i] = Wg[i];
        if (tid < HD) bs[tid] = b[h * HD + tid] * scale;
    }
    for (int i = tid; i < 64 * HD / 4; i += 256) {
        int r  = i / (HD / 4);
        int c4 = (i % (HD / 4)) * 4;
        *(float4*)(Xs + r * HD + c4) =
            *(const float4*)(X + ((size_t)(n * SEQ + s0 + r)) * VD + h * HD + c4);
    }
    __syncthreads();

    const int ty = tid / 16;
    const int tx = tid % 16;

    float acc[4][4];
    #pragma unroll
    for (int i = 0; i < 4; i++)
        #pragma unroll
        for (int j = 0; j < 4; j++) acc[i][j] = 0.f;

    #pragma unroll 8
    for (int k = 0; k < HD; k++) {
        const float4 bv = *(const float4*)(Ws + k * HD + tx * 4);
        #pragma unroll
        for (int i = 0; i < 4; i++) {
            const float a = Xs[(ty * 4 + i) * HD + k];
            acc[i][0] += a * bv.x; acc[i][1] += a * bv.y;
            acc[i][2] += a * bv.z; acc[i][3] += a * bv.w;
        }
    }

    #pragma unroll
    for (int i = 0; i < 4; i++) {
        const int s = s0 + ty * 4 + i;
        float4 o;
        o.x = acc[i][0] * scale + bs[tx * 4 + 0];
        o.y = acc[i][1] * scale + bs[tx * 4 + 1];
        o.z = acc[i][2] * scale + bs[tx * 4 + 2];
        o.w = acc[i][3] * scale + bs[tx * 4 + 3];
        *(float4*)(Y + ((size_t)((n * H + h) * SEQ + s)) * HD + tx * 4) = o;
    }
}

// ---------------------------------------------------------------------------
// Kernel 2: flash attention per (n,h), tf32 tensor-core MMAs, register softmax.
// Block 256 = 8 warps; warp w owns q-rows [16w,16w+16). grid (SEQ/QT, H, NB).
// SMEM (all tf32 uints, row stride PAD=68):
//   QsU[128][68] | SsU[128][68] (P) | KsU[64][68] | VsU[64][68] | msk[64]
// Fragment maps (m16n8k8, lane = 4g+t):
//   A: a0(g,t) a1(g+8,t) a2(g,t+4) a3(g+8,t+4)   [row-major m x k]
//   B: b0(t,g) b1(t+4,g)                          [col-major k x n]
//   C: c0(g,2t) c1(g,2t+1) c2(g+8,2t) c3(g+8,2t+1)
// ---------------------------------------------------------------------------
#define ATTN_SMEM_BYTES (((QT + QT + KT + KT) * PAD) * 4 + KT * 4)

__global__ __launch_bounds__(256, 2) void attn_kernel(const int* __restrict__ mask)
{
    extern __shared__ unsigned smu[];
    unsigned* QsU = smu;                   // [QT][PAD]
    unsigned* SsU = QsU + QT * PAD;        // [QT][PAD]  (P tile)
    unsigned* KsU = SsU + QT * PAD;        // [KT][PAD]  natural [kv][d]
    unsigned* VsU = KsU + KT * PAD;        // [KT][PAD]  natural [kv][d]
    int*      msk = (int*)(VsU + KT * PAD);

    const int h = blockIdx.y, n = blockIdx.z;
    const int q0 = blockIdx.x * QT;
    const int tid  = threadIdx.x;
    const int wid  = tid >> 5;
    const int lane = tid & 31;
    const int g = lane >> 2;
    const int t = lane & 3;
    const int qrow = wid * 16;

    const size_t head_off = (size_t)(n * H + h) * SEQ * HD;
    const float* Qg = g_Qp + head_off + (size_t)q0 * HD;
    const float* Kg = g_Kp + head_off;
    const float* Vg = g_Vp + head_off;

    // stage Q as tf32 (natural layout [q][d])
    for (int i = tid; i < QT * HD / 4; i += 256) {
        const int r  = i >> 4;
        const int c4 = (i & 15) * 4;
        const float4 q = *(const float4*)(Qg + (size_t)r * HD + c4);
        unsigned* dst = QsU + r * PAD + c4;
        dst[0] = f2tf(q.x); dst[1] = f2tf(q.y); dst[2] = f2tf(q.z); dst[3] = f2tf(q.w);
    }

    float O[8][4];
    #pragma unroll
    for (int j = 0; j < 8; j++)
        #pragma unroll
        for (int i = 0; i < 4; i++) O[j][i] = 0.f;
    float m0 = -1e30f, m1 = -1e30f, l0 = 0.f, l1 = 0.f;

    for (int kb = 0; kb < SEQ / KT; kb++) {
        __syncthreads();   // previous iteration consumers done (also covers Q stage at kb=0)
        const int kv0 = kb * KT;

        // load K and V tiles (natural [kv][d], tf32)
        for (int i = tid; i < KT * HD / 4; i += 256) {
            const int r  = i >> 4;
            const int c4 = (i & 15) * 4;
            const float4 kk = *(const float4*)(Kg + (size_t)(kv0 + r) * HD + c4);
            unsigned* kd = KsU + r * PAD + c4;
            kd[0] = f2tf(kk.x); kd[1] = f2tf(kk.y); kd[2] = f2tf(kk.z); kd[3] = f2tf(kk.w);
            const float4 vv = *(const float4*)(Vg + (size_t)(kv0 + r) * HD + c4);
            unsigned* vd = VsU + r * PAD + c4;
            vd[0] = f2tf(vv.x); vd[1] = f2tf(vv.y); vd[2] = f2tf(vv.z); vd[3] = f2tf(vv.w);
        }
        if (tid < KT) msk[tid] = mask[n * SEQ + kv0 + tid];
        __syncthreads();

        // ---- GEMM1: S[16 x 64] = Q · Kᵀ  (B(k=d, n=kv) col-major = K[kv][d]) ----
        float S[8][4];
        #pragma unroll
        for (int j = 0; j < 8; j++)
            #pragma unroll
            for (int i = 0; i < 4; i++) S[j][i] = 0.f;

        #pragma unroll
        for (int kk = 0; kk < 8; kk++) {
            const unsigned a0 = QsU[(qrow + g)     * PAD + kk * 8 + t];
            const unsigned a1 = QsU[(qrow + g + 8) * PAD + kk * 8 + t];
            const unsigned a2 = QsU[(qrow + g)     * PAD + kk * 8 + t + 4];
            const unsigned a3 = QsU[(qrow + g + 8) * PAD + kk * 8 + t + 4];
            #pragma unroll
            for (int j = 0; j < 8; j++) {
                const unsigned b0 = KsU[(j * 8 + g) * PAD + kk * 8 + t];
                const unsigned b1 = KsU[(j * 8 + g) * PAD + kk * 8 + t + 4];
                mma_tf32(S[j], a0, a1, a2, a3, b0, b1);
            }
        }

        // ---- mask + online softmax (register-resident, C-frag layout) ----
        #pragma unroll
        for (int j = 0; j < 8; j++) {
            if (msk[j * 8 + 2 * t]     == 0) { S[j][0] = -1e30f; S[j][2] = -1e30f; }
            if (msk[j * 8 + 2 * t + 1] == 0) { S[j][1] = -1e30f; S[j][3] = -1e30f; }
        }
        float mn0 = m0, mn1 = m1;
        #pragma unroll
        for (int j = 0; j < 8; j++) {
            mn0 = fmaxf(mn0, fmaxf(S[j][0], S[j][1]));
            mn1 = fmaxf(mn1, fmaxf(S[j][2], S[j][3]));
        }
        mn0 = fmaxf(mn0, __shfl_xor_sync(0xffffffffu, mn0, 1));
        mn0 = fmaxf(mn0, __shfl_xor_sync(0xffffffffu, mn0, 2));
        mn1 = fmaxf(mn1, __shfl_xor_sync(0xffffffffu, mn1, 1));
        mn1 = fmaxf(mn1, __shfl_xor_sync(0xffffffffu, mn1, 2));

        const float al0 = __expf(m0 - mn0);
        const float al1 = __expf(m1 - mn1);
        m0 = mn0; m1 = mn1;

        float s0 = 0.f, s1 = 0.f;
        unsigned* Prow0 = SsU + (qrow + g)     * PAD + 2 * t;
        unsigned* Prow1 = SsU + (qrow + g + 8) * PAD + 2 * t;
        #pragma unroll
        for (int j = 0; j < 8; j++) {
            const float p00 = __expf(S[j][0] - mn0);
            const float p01 = __expf(S[j][1] - mn0);
            const float p10 = __expf(S[j][2] - mn1);
            const float p11 = __expf(S[j][3] - mn1);
            s0 += p00 + p01;
            s1 += p10 + p11;
            *(uint2*)(Prow0 + j * 8) = make_uint2(f2tf(p00), f2tf(p01));
            *(uint2*)(Prow1 + j * 8) = make_uint2(f2tf(p10), f2tf(p11));
        }
        s0 += __shfl_xor_sync(0xffffffffu, s0, 1);
        s0 += __shfl_xor_sync(0xffffffffu, s0, 2);
        s1 += __shfl_xor_sync(0xffffffffu, s1, 1);
        s1 += __shfl_xor_sync(0xffffffffu, s1, 2);
        l0 = l0 * al0 + s0;
        l1 = l1 * al1 + s1;

        #pragma unroll
        for (int j = 0; j < 8; j++) {
            O[j][0] *= al0; O[j][1] *= al0;
            O[j][2] *= al1; O[j][3] *= al1;
        }
        __syncwarp();   // P stores visible to sibling lanes (Ss is per-warp private)

        // ---- GEMM2: O[16 x 64] += P · V  (B(k=kv, n=d) col-major = V[kv][d]) ----
        #pragma unroll
        for (int kk = 0; kk < 8; kk++) {
            const unsigned a0 = SsU[(qrow + g)     * PAD + kk * 8 + t];
            const unsigned a1 = SsU[(qrow + g + 8) * PAD + kk * 8 + t];
            const unsigned a2 = SsU[(qrow + g)     * PAD + kk * 8 + t + 4];
            const unsigned a3 = SsU[(qrow + g + 8) * PAD + kk * 8 + t + 4];
            #pragma unroll
            for (int j = 0; j < 8; j++) {
                const unsigned b0 = VsU[(kk * 8 + t)     * PAD + j * 8 + g];
                const unsigned b1 = VsU[(kk * 8 + t + 4) * PAD + j * 8 + g];
                mma_tf32(O[j], a0, a1, a2, a3, b0, b1);
            }
        }
    }

    // epilogue: normalize, write g_att[n, q, h*64+d]
    const float inv0 = 1.f / l0, inv1 = 1.f / l1;
    float* Og = g_att + ((size_t)n * SEQ + q0 + qrow) * VD + h * HD;
    #pragma unroll
    for (int j = 0; j < 8; j++) {
        float2 o0 = make_float2(O[j][0] * inv0, O[j][1] * inv0);
        float2 o1 = make_float2(O[j][2] * inv1, O[j][3] * inv1);
        *(float2*)(Og + (size_t)g       * VD + j * 8 + 2 * t) = o0;
        *(float2*)(Og + (size_t)(g + 8) * VD + j * 8 + 2 * t) = o1;
    }
}

// ---------------------------------------------------------------------------
// Kernel 3: output projection  out[s,j] = sum_d g_att[s,d] * Wo[j,d] + bo[j]
// (kept fp32 FFMA this round for precision headroom)
// ---------------------------------------------------------------------------
#define WTM 128
#define WTN 128
#define WTK 16

__global__ __launch_bounds__(256, 2) void wo_kernel(
    const float* __restrict__ Wo, const float* __restrict__ bo,
    float* __restrict__ out)
{
    __shared__ float As[WTM * WTK];   // [r][k]
    __shared__ float Bs[WTK * WTN];   // [k][j]

    const int j0 = blockIdx.x * WTN;
    const int r0 = blockIdx.y * WTM;
    const int tid = threadIdx.x;
    const int ty = tid / 16;
    const int tx = tid % 16;

    float acc[8][8];
    #pragma unroll
    for (int i = 0; i < 8; i++)
        #pragma unroll
        for (int j = 0; j < 8; j++) acc[i][j] = 0.f;

    for (int k0 = 0; k0 < VD; k0 += WTK) {
        __syncthreads();
        for (int i = tid; i < WTM * WTK / 4; i += 256) {
            const int r  = i >> 2;
            const int k4 = (i & 3) * 4;
            *(float4*)(As + r * WTK + k4) =
                *(const float4*)(g_att + (size_t)(r0 + r) * VD + k0 + k4);
        }
        for (int i = tid; i < WTN * WTK / 4; i += 256) {
            const int j  = i >> 2;
            const int k4 = (i & 3) * 4;
            const float4 w = *(const float4*)(Wo + (size_t)(j0 + j) * VD + k0 + k4);
            Bs[(k4 + 0) * WTN + j] = w.x;
            Bs[(k4 + 1) * WTN + j] = w.y;
            Bs[(k4 + 2) * WTN + j] = w.z;
            Bs[(k4 + 3) * WTN + j] = w.w;
        }
        __syncthreads();

        #pragma unroll
        for (int k = 0; k < WTK; k++) {
            const float4 b0 = *(const float4*)(Bs + k * WTN + tx * 8);
            const float4 b1 = *(const float4*)(Bs + k * WTN + tx * 8 + 4);
            float a[8];
            #pragma unroll
            for (int i = 0; i < 8; i++) a[i] = As[(ty * 8 + i) * WTK + k];
            #pragma unroll
            for (int i = 0; i < 8; i++) {
                acc[i][0] += a[i] * b0.x; acc[i][1] += a[i] * b0.y;
                acc[i][2] += a[i] * b0.z; acc[i][3] += a[i] * b0.w;
                acc[i][4] += a[i] * b1.x; acc[i][5] += a[i] * b1.y;
                acc[i][6] += a[i] * b1.z; acc[i][7] += a[i] * b1.w;
            }
        }
    }

    const float4 bb0 = *(const float4*)(bo + j0 + tx * 8);
    const float4 bb1 = *(const float4*)(bo + j0 + tx * 8 + 4);
    #pragma unroll
    for (int i = 0; i < 8; i++) {
        const int r = r0 + ty * 8 + i;
        float4 o0, o1;
        o0.x = acc[i][0] + bb0.x; o0.y = acc[i][1] + bb0.y;
        o0.z = acc[i][2] + bb0.z; o0.w = acc[i][3] + bb0.w;
        o1.x = acc[i][4] + bb1.x; o1.y = acc[i][5] + bb1.y;
        o1.z = acc[i][6] + bb1.z; o1.w = acc[i][7] + bb1.w;
        *(float4*)(out + (size_t)r * VD + j0 + tx * 8)     = o0;
        *(float4*)(out + (size_t)r * VD + j0 + tx * 8 + 4) = o1;
    }
}

// ---------------------------------------------------------------------------
// Host launcher (graph-capturable: kernel launches only)
// ---------------------------------------------------------------------------
extern "C" void kernel_launch(void* const* d_in, const int* in_sizes, int n_in,
                              void* d_out, int out_size)
{
    const float* values = (const float*)d_in[0];
    const float* keys   = (const float*)d_in[1];
    const float* query  = (const float*)d_in[2];
    const int*   mask   = (const int*)  d_in[3];
    const float* Wv     = (const float*)d_in[4];
    const float* bv     = (const float*)d_in[5];
    const float* Wk     = (const float*)d_in[6];
    const float* bk     = (const float*)d_in[7];
    const float* Wq     = (const float*)d_in[8];
    const float* bq     = (const float*)d_in[9];
    const float* Wo     = (const float*)d_in[10];
    const float* bo     = (const float*)d_in[11];
    float* out = (float*)d_out;

    cudaFuncSetAttribute(attn_kernel, cudaFuncAttributeMaxDynamicSharedMemorySize,
                         ATTN_SMEM_BYTES);

    const dim3 pgrid(SEQ / 64, H, NB);
    // Q projection pre-scaled by 1/sqrt(VOXEL_DIM) = 1/32
    proj_kernel<<<pgrid, 256>>>(query,  Wq, bq, /*dst=*/0, 1.0f / 32.0f);
    proj_kernel<<<pgrid, 256>>>(keys,   Wk, bk, /*dst=*/1, 1.0f);
    proj_kernel<<<pgrid, 256>>>(values, Wv, bv, /*dst=*/2, 1.0f);

    attn_kernel<<<dim3(SEQ / QT, H, NB), 256, ATTN_SMEM_BYTES>>>(mask);

    wo_kernel<<<dim3(VD / WTN, (NB * SEQ) / WTM), 256>>>(Wo, bo, out);
}